// round 4
// baseline (speedup 1.0000x reference)
#include <cuda_runtime.h>
#include <cstdint>

#define D_   256
#define Z_   32
#define B_   128
#define T_   1000
#define EPS_ 1e-6f
#define NOUT ((size_t)B_ * T_ * D_)
#define JPC  160
#define JPAD 164
#define STH  320

__device__ float g_z[(size_t)B_ * T_ * Z_];   // [b][t][z]
__device__ float g_U[(size_t)B_ * T_ * D_];   // t-major: [t][b][256]
__device__ float g_kl[64];
__device__ int   g_flag[T_];

__device__ __forceinline__ float tanh_s(float x) {
    float ax = fabsf(x);
    float e = __expf(-2.0f * ax);
    return copysignf((1.0f - e) / (1.0f + e), x);
}
__device__ __forceinline__ uint32_t smem_u32(const void* p) {
    uint32_t a;
    asm("{ .reg .u64 t; cvta.to.shared.u64 t, %1; cvt.u32.u64 %0, t; }" : "=r"(a) : "l"(p));
    return a;
}
__device__ __forceinline__ int ld_acq(const int* p) {
    int v;
    asm volatile("ld.acquire.gpu.global.b32 %0, [%1];" : "=r"(v) : "l"(p) : "memory");
    return v;
}

// ---- reset flags ----
__global__ void reset_flags() {
    int i = blockIdx.x * 256 + threadIdx.x;
    if (i < T_) g_flag[i] = 0;
}

// ---- z = tanh(A[:, :Z]) + noise * exp(A[:, Z:]) ----
__global__ __launch_bounds__(256) void z_kernel(const float* __restrict__ A,
                                                const float* __restrict__ nz) {
    int i = blockIdx.x * 256 + threadIdx.x;
    if (i >= B_ * T_ * Z_) return;
    int m = i >> 5, z = i & 31;
    g_z[i] = tanh_s(A[(size_t)m * 64 + z]) + nz[i] * __expf(A[(size_t)m * 64 + 32 + z]);
}

// ---- U[t][b][:] = hd[b][t]@Whd2h^T + z[b][t]@Wz2h^T + bias ; per-t flags ----
__global__ __launch_bounds__(256, 1) void u_gemm(const float* __restrict__ hd,
                                                 const float* __restrict__ Wh,
                                                 const float* __restrict__ Wz,
                                                 const float* __restrict__ bias) {
    __shared__ float As[8][128], Bs[8][128];
    int tid = threadIdx.x;
    const int y = blockIdx.y;            // timestep
    const int mB = y * 128, nB = blockIdx.x * 128;
    int lr = tid >> 1, lk = (tid & 1) << 2;
    int tr = (tid >> 4) << 3, tc = (tid & 15) << 3;
    // A-row for this thread: batch = lr, timestep = y (b-major inputs)
    const float* aRow = hd  + ((size_t)lr * 1000 + y) * 256;
    const float* zRow = g_z + ((size_t)lr * 1000 + y) * 32;
    const float* bRowH = Wh + (size_t)(nB + lr) * 256;
    const float* bRowZ = Wz + (size_t)(nB + lr) * 32;

    float acc[8][8];
#pragma unroll
    for (int i = 0; i < 8; i++)
#pragma unroll
        for (int j = 0; j < 8; j++) acc[i][j] = 0.f;

    for (int k0 = 0; k0 < 288; k0 += 8) {
        float4 av, bv;
        if (k0 < 256) {
            av = *(const float4*)(aRow + k0 + lk);
            bv = *(const float4*)(bRowH + k0 + lk);
        } else {
            av = *(const float4*)(zRow + (k0 - 256) + lk);
            bv = *(const float4*)(bRowZ + (k0 - 256) + lk);
        }
        __syncthreads();
        As[lk][lr] = av.x; As[lk + 1][lr] = av.y; As[lk + 2][lr] = av.z; As[lk + 3][lr] = av.w;
        Bs[lk][lr] = bv.x; Bs[lk + 1][lr] = bv.y; Bs[lk + 2][lr] = bv.z; Bs[lk + 3][lr] = bv.w;
        __syncthreads();
#pragma unroll
        for (int kk = 0; kk < 8; kk++) {
            float mf[8], nf[8];
            *(float4*)mf = *(const float4*)&As[kk][tr];
            *(float4*)(mf + 4) = *(const float4*)&As[kk][tr + 4];
            *(float4*)nf = *(const float4*)&Bs[kk][tc];
            *(float4*)(nf + 4) = *(const float4*)&Bs[kk][tc + 4];
#pragma unroll
            for (int i = 0; i < 8; i++)
#pragma unroll
                for (int j = 0; j < 8; j++) acc[i][j] += mf[i] * nf[j];
        }
    }
    float bj[8];
#pragma unroll
    for (int j = 0; j < 8; j++) bj[j] = bias[nB + tc + j];
#pragma unroll
    for (int i = 0; i < 8; i++) {
        float* o = g_U + (size_t)(mB + tr + i) * 256 + nB + tc;
#pragma unroll
        for (int j = 0; j < 8; j++) o[j] = acc[i][j] + bj[j];
    }
    __syncthreads();
    if (tid == 0) {
        __threadfence();
        atomicAdd(&g_flag[y], 1);
    }
}

// ---- wnll_init_h ----
__global__ __launch_bounds__(256) void wnll_kernel(const float* __restrict__ ih,
                                                   const float* __restrict__ mu,
                                                   float* __restrict__ out) {
    __shared__ float sr[8];
    int tid = threadIdx.x;
    float s = 0.f;
    for (int i = tid; i < B_ * D_; i += 256) {
        float d = ih[i] - mu[i & 255];
        s += 0.5f * d * d + 0.91893853320467274f;
    }
#pragma unroll
    for (int o = 16; o > 0; o >>= 1) s += __shfl_down_sync(~0u, s, o);
    if ((tid & 31) == 0) sr[tid >> 5] = s;
    __syncthreads();
    if (tid == 0) {
        float t = 0.f;
        for (int i = 0; i < 8; i++) t += sr[i];
        out[NOUT + 1] = 0.001f * t / 256.0f;
    }
}

// ---- kl final reduce ----
__global__ void kl_final(float* __restrict__ out) {
    if (threadIdx.x == 0) {
        float s = 0.f;
        for (int i = 0; i < 64; i++) s += g_kl[i];
        out[NOUT] = 0.001f / 32.0f * s;
    }
}

// ---- sequential scan: 64 clusters x 2 CTAs, 2 batch rows per cluster ----
__global__ void __cluster_dims__(2, 1, 1) __launch_bounds__(STH, 1)
seq_kernel(const float* __restrict__ A, const float* __restrict__ in_p0,
           const float* __restrict__ Wd2h, const float* __restrict__ Wd2z,
           const float* __restrict__ initH, float* __restrict__ out) {
    extern __shared__ float sm[];
    float* Ws   = sm;                 // [256][JPAD] k-major
    float* dbuf = Ws + 256 * JPAD;    // [2][2][256]
    float* red  = dbuf + 1024;        // [8][40][2][4]
    float* dzs  = red + 2560;         // [2][64]

    const int tid = threadIdx.x;
    const int rank = blockIdx.x & 1;
    const int c = blockIdx.x >> 1;

    const int jg = tid % 40, ks = tid / 40, kb = ks * 32;
    const int uj = tid % JPC, ub = tid / JPC;
    const int ng = rank * JPC + uj;
    const bool has_h = (ng < 256);
    const int b_u = 2 * c + ub;
    const float dec = (ng < 128) ? 0.75f : 0.5f;
    const float itau = (ng < 128) ? 0.25f : 0.5f;

    const bool isKL = (rank == 1) && (tid < 64);
    const int klb = tid >> 5, klz = tid & 31;
    float p0m = 0.f, p0s = 0.f;
    const float* Ap = A + (size_t)(2 * c + klb) * T_ * 64;
    if (isKL) {
        p0m = in_p0[(2 * c + klb) * 64 + klz];
        p0s = in_p0[(2 * c + klb) * 64 + 32 + klz];
    }

    for (int i = tid; i < JPC * 256; i += STH) {
        int j = i >> 8, k = i & 255, n = rank * JPC + j;
        Ws[k * JPAD + j] = (n < 256) ? Wd2h[n * 256 + k] : Wd2z[(n - 256) * 256 + k];
    }
    for (int i = tid; i < 512; i += STH) {
        int bb = i >> 8, k = i & 255;
        dbuf[bb * 256 + k] = tanh_s(initH[(2 * c + bb) * 256 + k]);
    }
    float h = 0.f;
    const float* Up = g_U;
    float* Op = out;
    if (has_h) {
        h = initH[b_u * 256 + ng];
        Up = g_U + (size_t)b_u * 256 + ng;               // t-major: row t*128+b
        Op = out + (size_t)b_u * T_ * 256 + ng;          // output stays b-major
    }
    const uint32_t dl = smem_u32(dbuf);
    uint32_t dp;
    asm("mapa.shared::cluster.u32 %0, %1, %2;" : "=r"(dp) : "r"(dl), "r"(rank ^ 1));

    __syncthreads();

    // prologue prefetch t=0
    float u_pf = 0.f, amu = 0.f, als = 0.f;
    if (has_h) {
        while (ld_acq(&g_flag[0]) < 2) {}
        u_pf = __ldg(Up);
    }
    if (isKL) { amu = __ldg(Ap + klz); als = __ldg(Ap + 32 + klz); }

    float klacc = 0.f;
    int cur = 0;
    for (int t = 0; t < T_; ++t) {
        if (t > 0)
            asm volatile("barrier.cluster.wait.aligned;" ::: "memory");

        const float* dc = dbuf + cur * 512;
        float a0 = 0, a1 = 0, a2 = 0, a3 = 0, b0 = 0, b1 = 0, b2 = 0, b3 = 0;
        const float4* wr = (const float4*)(Ws + kb * JPAD) + jg;
#pragma unroll 8
        for (int k = 0; k < 32; ++k) {
            float4 w = wr[k * (JPAD / 4)];
            float d0 = dc[kb + k], d1 = dc[256 + kb + k];
            a0 += w.x * d0; a1 += w.y * d0; a2 += w.z * d0; a3 += w.w * d0;
            b0 += w.x * d1; b1 += w.y * d1; b2 += w.z * d1; b3 += w.w * d1;
        }
        float4* r4 = (float4*)red + ((size_t)ks * 40 + jg) * 2;
        r4[0] = make_float4(a0, a1, a2, a3);
        r4[1] = make_float4(b0, b1, b2, b3);
        __syncthreads();

        float f = 0.f;
        const float* rp = red + (uj >> 2) * 8 + ub * 4 + (uj & 3);
#pragma unroll
        for (int s = 0; s < 8; ++s) f += rp[s * 320];

        int nxt = cur ^ 1;
        if (has_h) {
            h = dec * h + itau * (f + u_pf);
            float dn = tanh_s(h);
            int off = nxt * 512 + ub * 256 + ng;
            dbuf[off] = dn;
            asm volatile("st.shared::cluster.b32 [%0], %1;" :: "r"(dp + off * 4),
                         "r"(__float_as_uint(dn)) : "memory");
            *Op = dn;
            Op += 256;
        } else {
            dzs[ub * 64 + (uj - 96)] = f;
        }

        if (rank == 1) {
            __syncthreads();
            if (tid < 64) {
                float mq = tanh_s(amu), sq = __expf(als);
                float pm = (t == 0) ? p0m : dzs[klb * 64 + klz];
                float ps = (t == 0) ? p0s : dzs[klb * 64 + 32 + klz];
                float mp = tanh_s(pm), sp = __expf(ps);
                float dm = mq - mp;
                klacc += __logf(sp + EPS_) - __logf(sq + EPS_) - 0.5f
                       + 0.5f * (dm * dm + sq * sq) / (sp * sp + EPS_);
            }
        }

        asm volatile("barrier.cluster.arrive.aligned;" ::: "memory");

        // prefetch t+1 while peer catches up (hides barrier + flag latency)
        if (t + 1 < T_) {
            if (has_h) {
                Up += 128 * 256;
                while (ld_acq(&g_flag[t + 1]) < 2) {}
                u_pf = __ldg(Up);
            }
            if (isKL) {
                Ap += 64;
                amu = __ldg(Ap + klz);
                als = __ldg(Ap + 32 + klz);
            }
        }
        cur = nxt;
    }
    asm volatile("barrier.cluster.wait.aligned;" ::: "memory");

    if (rank == 1) {
        if (tid < 64) red[tid] = klacc;
        __syncthreads();
        if (tid == 0) {
            float s = 0.f;
            for (int i = 0; i < 64; i++) s += red[i];
            g_kl[c] = s;
        }
    }
}

extern "C" void kernel_launch(void* const* d_in, const int* in_sizes, int n_in,
                              void* d_out, int out_size) {
    const float* hd    = (const float*)d_in[0];
    const float* A     = (const float*)d_in[1];
    const float* in_p0 = (const float*)d_in[2];
    const float* noise = (const float*)d_in[3];
    const float* Wd2h  = (const float*)d_in[4];
    const float* Wz2h  = (const float*)d_in[5];
    const float* Wd2z  = (const float*)d_in[6];
    const float* Whd2h = (const float*)d_in[7];
    const float* biasd = (const float*)d_in[8];
    const float* initH = (const float*)d_in[9];
    const float* ihmu  = (const float*)d_in[10];
    float* out = (float*)d_out;

    static cudaStream_t s2 = nullptr;
    static cudaEvent_t e1 = nullptr, e2 = nullptr;
    if (!s2) {
        cudaStreamCreateWithFlags(&s2, cudaStreamNonBlocking);
        cudaEventCreateWithFlags(&e1, cudaEventDisableTiming);
        cudaEventCreateWithFlags(&e2, cudaEventDisableTiming);
    }

    // main stream: reset flags, then fork producer branch
    reset_flags<<<4, 256>>>();
    wnll_kernel<<<1, 256>>>(initH, ihmu, out);

    cudaEventRecord(e1, 0);
    cudaStreamWaitEvent(s2, e1, 0);
    z_kernel<<<(B_ * T_ * Z_ + 255) / 256, 256, 0, s2>>>(A, noise);
    u_gemm<<<dim3(2, 1000), 256, 0, s2>>>(hd, Whd2h, Wz2h, biasd);
    cudaEventRecord(e2, s2);

    // consumer branch (concurrent with producer)
    const int smem = (256 * JPAD + 1024 + 2560 + 128) * 4;
    cudaFuncSetAttribute(seq_kernel, cudaFuncAttributeMaxDynamicSharedMemorySize, smem);
    seq_kernel<<<128, STH, smem>>>(A, in_p0, Wd2h, Wd2z, initH, out);
    kl_final<<<1, 32>>>(out);

    // join producer branch so the graph's end covers it
    cudaStreamWaitEvent(0, e2, 0);
}

// round 5
// speedup vs baseline: 1.4051x; 1.4051x over previous
#include <cuda_runtime.h>
#include <cstdint>

#define D_   256
#define Z_   32
#define B_   128
#define T_   1000
#define EPS_ 1e-6f
#define NOUT ((size_t)B_ * T_ * D_)
#define JPAD 164
#define STH  320

__device__ float g_z[(size_t)B_ * T_ * Z_];
__device__ float g_U[(size_t)B_ * T_ * D_];
__device__ float g_kl[64];

__device__ __forceinline__ float tanh_s(float x) {
    float ax = fabsf(x);
    float e = __expf(-2.0f * ax);
    return copysignf((1.0f - e) / (1.0f + e), x);
}
__device__ __forceinline__ uint32_t smem_u32(const void* p) {
    uint32_t a;
    asm("{ .reg .u64 t; cvta.to.shared.u64 t, %1; cvt.u32.u64 %0, t; }" : "=r"(a) : "l"(p));
    return a;
}

// ---- z = tanh(A[:, :Z]) + noise * exp(A[:, Z:]) ----
__global__ __launch_bounds__(256) void z_kernel(const float* __restrict__ A,
                                                const float* __restrict__ nz) {
    int i = blockIdx.x * 256 + threadIdx.x;
    if (i >= B_ * T_ * Z_) return;
    int m = i >> 5, z = i & 31;
    g_z[i] = tanh_s(A[(size_t)m * 64 + z]) + nz[i] * __expf(A[(size_t)m * 64 + 32 + z]);
}

// ---- U = hd@Whd2h^T + z@Wz2h^T + bias : M=128000 N=256 K=288, dbl-buffered ----
__global__ __launch_bounds__(256, 1) void u_gemm(const float* __restrict__ hd,
                                                 const float* __restrict__ Wh,
                                                 const float* __restrict__ Wz,
                                                 const float* __restrict__ bias) {
    __shared__ float As[2][8][128], Bs[2][8][128];
    int tid = threadIdx.x;
    int mB = blockIdx.y * 128, nB = blockIdx.x * 128;
    int lr = tid >> 1, lk = (tid & 1) << 2;
    int tr = (tid >> 4) << 3, tc = (tid & 15) << 3;
    float acc[8][8];
#pragma unroll
    for (int i = 0; i < 8; i++)
#pragma unroll
        for (int j = 0; j < 8; j++) acc[i][j] = 0.f;

    const float* aH = hd + (size_t)(mB + lr) * 256 + lk;
    const float* bH = Wh + (size_t)(nB + lr) * 256 + lk;
    const float* aZ = g_z + (size_t)(mB + lr) * 32 + lk;
    const float* bZ = Wz + (size_t)(nB + lr) * 32 + lk;

    float4 av = *(const float4*)(aH);
    float4 bv = *(const float4*)(bH);
    As[0][lk][lr] = av.x; As[0][lk + 1][lr] = av.y; As[0][lk + 2][lr] = av.z; As[0][lk + 3][lr] = av.w;
    Bs[0][lk][lr] = bv.x; Bs[0][lk + 1][lr] = bv.y; Bs[0][lk + 2][lr] = bv.z; Bs[0][lk + 3][lr] = bv.w;
    __syncthreads();

    int p = 0;
    for (int k0 = 0; k0 < 288; k0 += 8) {
        float4 nav, nbv;
        bool more = (k0 < 280);
        if (more) {
            int kn = k0 + 8;
            if (kn < 256) {
                nav = *(const float4*)(aH + kn);
                nbv = *(const float4*)(bH + kn);
            } else {
                nav = *(const float4*)(aZ + (kn - 256));
                nbv = *(const float4*)(bZ + (kn - 256));
            }
        }
#pragma unroll
        for (int kk = 0; kk < 8; kk++) {
            float mf[8], nf[8];
            *(float4*)mf = *(const float4*)&As[p][kk][tr];
            *(float4*)(mf + 4) = *(const float4*)&As[p][kk][tr + 4];
            *(float4*)nf = *(const float4*)&Bs[p][kk][tc];
            *(float4*)(nf + 4) = *(const float4*)&Bs[p][kk][tc + 4];
#pragma unroll
            for (int i = 0; i < 8; i++)
#pragma unroll
                for (int j = 0; j < 8; j++) acc[i][j] += mf[i] * nf[j];
        }
        if (more) {
            int q = p ^ 1;
            As[q][lk][lr] = nav.x; As[q][lk + 1][lr] = nav.y; As[q][lk + 2][lr] = nav.z; As[q][lk + 3][lr] = nav.w;
            Bs[q][lk][lr] = nbv.x; Bs[q][lk + 1][lr] = nbv.y; Bs[q][lk + 2][lr] = nbv.z; Bs[q][lk + 3][lr] = nbv.w;
            p = q;
            __syncthreads();
        }
    }
    float bj[8];
#pragma unroll
    for (int j = 0; j < 8; j++) bj[j] = bias[nB + tc + j];
#pragma unroll
    for (int i = 0; i < 8; i++) {
        float* o = g_U + (size_t)(mB + tr + i) * 256 + nB + tc;
#pragma unroll
        for (int j = 0; j < 8; j++) o[j] = acc[i][j] + bj[j];
    }
}

// ---- wnll_init_h ----
__global__ __launch_bounds__(256) void wnll_kernel(const float* __restrict__ ih,
                                                   const float* __restrict__ mu,
                                                   float* __restrict__ out) {
    __shared__ float sr[8];
    int tid = threadIdx.x;
    float s = 0.f;
    for (int i = tid; i < B_ * D_; i += 256) {
        float d = ih[i] - mu[i & 255];
        s += 0.5f * d * d + 0.91893853320467274f;
    }
#pragma unroll
    for (int o = 16; o > 0; o >>= 1) s += __shfl_down_sync(~0u, s, o);
    if ((tid & 31) == 0) sr[tid >> 5] = s;
    __syncthreads();
    if (tid == 0) {
        float t = 0.f;
        for (int i = 0; i < 8; i++) t += sr[i];
        out[NOUT + 1] = 0.001f * t / 256.0f;
    }
}

// ---- kl final reduce ----
__global__ void kl_final(float* __restrict__ out) {
    if (threadIdx.x == 0) {
        float s = 0.f;
        for (int i = 0; i < 64; i++) s += g_kl[i];
        out[NOUT] = 0.001f / 32.0f * s;
    }
}

// ---- sequential scan: 64 clusters x 2 CTAs, warp-local k-split, 1 sync/step ----
__global__ void __cluster_dims__(2, 1, 1) __launch_bounds__(STH, 1)
seq_kernel(const float* __restrict__ A, const float* __restrict__ in_p0,
           const float* __restrict__ Wd2h, const float* __restrict__ Wd2z,
           const float* __restrict__ initH, float* __restrict__ out) {
    extern __shared__ float sm[];
    float* Ws   = sm;                  // [256][JPAD] k-major
    float* dbuf = Ws + 256 * JPAD;     // [2 buf][2 b][272]
    float* dzs  = dbuf + 1088;         // [2 buf][2 b][64]
    float* sred = dzs + 256;           // [16]

    const int tid = threadIdx.x;
    const int rank = blockIdx.x & 1;
    const int c = blockIdx.x >> 1;
    const int warp = tid >> 5, lane = tid & 31;
    const int j4sub = lane & 3, ks = lane >> 2;
    const int jcol = (warp * 4 + j4sub) * 4;               // weight col base
    const int jsel = ((ks & 2) ? 2 : 0) + ((ks & 4) ? 1 : 0);
    const int jmine = jcol + jsel;
    const int bmine = ks & 1;
    const int ng = rank * 160 + jmine;
    const bool has_h = (ng < 256);
    const int b_u = 2 * c + bmine;
    const float dec  = (ng < 128) ? 0.75f : 0.5f;
    const float itau = (ng < 128) ? 0.25f : 0.5f;

    const bool isKL = (rank == 1) && (tid < 64);
    const int klb = tid >> 5, klz = tid & 31;
    float p0m = 0.f, p0s = 0.f, amu_p = 0.f, als_p = 0.f;
    const float* Ap = A + (size_t)(2 * c + klb) * T_ * 64;
    if (isKL) {
        p0m = in_p0[(2 * c + klb) * 64 + klz];
        p0s = in_p0[(2 * c + klb) * 64 + 32 + klz];
    }

    // weights: this CTA's 160 output-columns, k-major with pad
    for (int i = tid; i < 160 * 256; i += STH) {
        int j = i >> 8, k = i & 255, n = rank * 160 + j;
        Ws[k * JPAD + j] = (n < 256) ? Wd2h[n * 256 + k] : Wd2z[(n - 256) * 256 + k];
    }
    // d0 = tanh(init_h), both batches, full 256
    for (int i = tid; i < 512; i += STH) {
        int bb = i >> 8, k = i & 255;
        dbuf[bb * 272 + k] = tanh_s(initH[(2 * c + bb) * 256 + k]);
    }
    float h = 0.f, u_pf = 0.f;
    const float* Up = g_U;
    float* Op = out;
    if (has_h) {
        h = initH[b_u * 256 + ng];
        Up = g_U + (size_t)b_u * T_ * 256 + ng;
        Op = out + (size_t)b_u * T_ * 256 + ng;
    }
    const uint32_t dl = smem_u32(dbuf);
    uint32_t dp;
    asm("mapa.shared::cluster.u32 %0, %1, %2;" : "=r"(dp) : "r"(dl), "r"(rank ^ 1));

    __syncthreads();
    asm volatile("barrier.cluster.arrive.aligned;\n\tbarrier.cluster.wait.aligned;" ::: "memory");

    if (has_h) u_pf = __ldg(Up);

    float klacc = 0.f;
    int cur = 0;
    for (int t = 0; t < T_; ++t) {
        if (t > 0) asm volatile("barrier.cluster.wait.aligned;" ::: "memory");

        // deferred KL for step t-1
        if (isKL && t > 0) {
            float mq = tanh_s(amu_p), sq = __expf(als_p);
            float pm, ps;
            if (t == 1) { pm = p0m; ps = p0s; }
            else {
                const float* dzp = dzs + ((t - 1) & 1) * 128 + klb * 64;
                pm = dzp[klz]; ps = dzp[32 + klz];
            }
            float mp = tanh_s(pm), sp = __expf(ps);
            float dm = mq - mp;
            klacc += __logf(sp + EPS_) - __logf(sq + EPS_) - 0.5f
                   + 0.5f * (dm * dm + sq * sq) / (sp * sp + EPS_);
        }

        // GEMM phase: lane covers k = ks*4 + r + 32*i, j = jcol..jcol+3, b = 0,1
        const float* dc = dbuf + cur * 544;
        const float* wb = Ws + jcol;
        float4 a0 = make_float4(0.f, 0.f, 0.f, 0.f);
        float4 a1 = make_float4(0.f, 0.f, 0.f, 0.f);
#pragma unroll
        for (int i = 0; i < 8; i++) {
            int kr = ks * 4 + 32 * i;
            float4 dv0 = *(const float4*)(dc + kr);
            float4 dv1 = *(const float4*)(dc + 272 + kr);
            float4 w0 = *(const float4*)(wb + (kr + 0) * JPAD);
            float4 w1 = *(const float4*)(wb + (kr + 1) * JPAD);
            float4 w2 = *(const float4*)(wb + (kr + 2) * JPAD);
            float4 w3 = *(const float4*)(wb + (kr + 3) * JPAD);
            a0.x += w0.x * dv0.x; a0.y += w0.y * dv0.x; a0.z += w0.z * dv0.x; a0.w += w0.w * dv0.x;
            a0.x += w1.x * dv0.y; a0.y += w1.y * dv0.y; a0.z += w1.z * dv0.y; a0.w += w1.w * dv0.y;
            a0.x += w2.x * dv0.z; a0.y += w2.y * dv0.z; a0.z += w2.z * dv0.z; a0.w += w2.w * dv0.z;
            a0.x += w3.x * dv0.w; a0.y += w3.y * dv0.w; a0.z += w3.z * dv0.w; a0.w += w3.w * dv0.w;
            a1.x += w0.x * dv1.x; a1.y += w0.y * dv1.x; a1.z += w0.z * dv1.x; a1.w += w0.w * dv1.x;
            a1.x += w1.x * dv1.y; a1.y += w1.y * dv1.y; a1.z += w1.z * dv1.y; a1.w += w1.w * dv1.y;
            a1.x += w2.x * dv1.z; a1.y += w2.y * dv1.z; a1.z += w2.z * dv1.z; a1.w += w2.w * dv1.z;
            a1.x += w3.x * dv1.w; a1.y += w3.y * dv1.w; a1.z += w3.z * dv1.w; a1.w += w3.w * dv1.w;
        }

        // butterfly reduce over ks (lane bits 2,3,4), halving payload
        float4 keep, send;
        if (bmine) { keep = a1; send = a0; } else { keep = a0; send = a1; }
        keep.x += __shfl_xor_sync(~0u, send.x, 4);
        keep.y += __shfl_xor_sync(~0u, send.y, 4);
        keep.z += __shfl_xor_sync(~0u, send.z, 4);
        keep.w += __shfl_xor_sync(~0u, send.w, 4);
        float k2x, k2y, s2x, s2y;
        if (ks & 2) { k2x = keep.z; k2y = keep.w; s2x = keep.x; s2y = keep.y; }
        else        { k2x = keep.x; k2y = keep.y; s2x = keep.z; s2y = keep.w; }
        k2x += __shfl_xor_sync(~0u, s2x, 8);
        k2y += __shfl_xor_sync(~0u, s2y, 8);
        float k3, s3;
        if (ks & 4) { k3 = k2y; s3 = k2x; } else { k3 = k2x; s3 = k2y; }
        float f = k3 + __shfl_xor_sync(~0u, s3, 16);
        // f = full dot for (j = jmine, b = bmine)

        int nxt = cur ^ 1;
        if (has_h) {
            h = dec * h + itau * (f + u_pf);
            float dn = tanh_s(h);
            int off = nxt * 544 + bmine * 272 + ng;
            dbuf[off] = dn;
            asm volatile("st.shared::cluster.b32 [%0], %1;" :: "r"(dp + (uint32_t)(off * 4)),
                         "r"(__float_as_uint(dn)) : "memory");
            *Op = dn;
            Op += 256;
        } else {
            dzs[(t & 1) * 128 + bmine * 64 + (jmine - 96)] = f;
        }

        asm volatile("barrier.cluster.arrive.aligned;" ::: "memory");

        // prefetch for next iter (hides barrier latency)
        if (has_h && t + 1 < T_) {
            Up += 256;
            u_pf = __ldg(Up);
        }
        if (isKL) {
            amu_p = __ldg(Ap + klz);
            als_p = __ldg(Ap + 32 + klz);
            Ap += 64;
        }
        cur = nxt;
    }
    asm volatile("barrier.cluster.wait.aligned;" ::: "memory");

    // final KL term (step T-1) + reduction
    if (isKL) {
        float mq = tanh_s(amu_p), sq = __expf(als_p);
        const float* dzp = dzs + ((T_ - 1) & 1) * 128 + klb * 64;
        float mp = tanh_s(dzp[klz]), sp = __expf(dzp[32 + klz]);
        float dm = mq - mp;
        klacc += __logf(sp + EPS_) - __logf(sq + EPS_) - 0.5f
               + 0.5f * (dm * dm + sq * sq) / (sp * sp + EPS_);
    }
    if (rank == 1) {
        float v = (tid < 64) ? klacc : 0.f;
#pragma unroll
        for (int o = 16; o > 0; o >>= 1) v += __shfl_down_sync(~0u, v, o);
        if (lane == 0) sred[warp] = v;
        __syncthreads();
        if (tid == 0) {
            float s = 0.f;
            for (int w = 0; w < 10; w++) s += sred[w];
            g_kl[c] = s;
        }
    }
}

extern "C" void kernel_launch(void* const* d_in, const int* in_sizes, int n_in,
                              void* d_out, int out_size) {
    const float* hd    = (const float*)d_in[0];
    const float* A     = (const float*)d_in[1];
    const float* in_p0 = (const float*)d_in[2];
    const float* noise = (const float*)d_in[3];
    const float* Wd2h  = (const float*)d_in[4];
    const float* Wz2h  = (const float*)d_in[5];
    const float* Wd2z  = (const float*)d_in[6];
    const float* Whd2h = (const float*)d_in[7];
    const float* biasd = (const float*)d_in[8];
    const float* initH = (const float*)d_in[9];
    const float* ihmu  = (const float*)d_in[10];
    float* out = (float*)d_out;

    z_kernel<<<(B_ * T_ * Z_ + 255) / 256, 256>>>(A, noise);
    u_gemm<<<dim3(2, 1000), 256>>>(hd, Whd2h, Wz2h, biasd);
    wnll_kernel<<<1, 256>>>(initH, ihmu, out);

    const int smem = (256 * JPAD + 1088 + 256 + 16) * 4;
    cudaFuncSetAttribute(seq_kernel, cudaFuncAttributeMaxDynamicSharedMemorySize, smem);
    seq_kernel<<<128, STH, smem>>>(A, in_p0, Wd2h, Wd2z, initH, out);
    kl_final<<<1, 32>>>(out);
}

// round 6
// speedup vs baseline: 1.5013x; 1.0685x over previous
#include <cuda_runtime.h>
#include <cstdint>

#define D_   256
#define Z_   32
#define B_   128
#define T_   1000
#define EPS_ 1e-6f
#define NOUT ((size_t)B_ * T_ * D_)
#define STH  320

typedef unsigned long long ull;

__device__ float g_z[(size_t)B_ * T_ * Z_];
__device__ float g_U[(size_t)B_ * T_ * D_];
__device__ float g_kl[64];

__device__ __forceinline__ float tanh_s(float x) {
    float ax = fabsf(x);
    float e = __expf(-2.0f * ax);
    return copysignf((1.0f - e) / (1.0f + e), x);
}
__device__ __forceinline__ uint32_t smem_u32(const void* p) {
    uint32_t a;
    asm("{ .reg .u64 t; cvta.to.shared.u64 t, %1; cvt.u32.u64 %0, t; }" : "=r"(a) : "l"(p));
    return a;
}
__device__ __forceinline__ void ffma2(ull& acc, ull w, ull d) {
    asm("fma.rn.f32x2 %0, %1, %2, %0;" : "+l"(acc) : "l"(w), "l"(d));
}
__device__ __forceinline__ float unpack_sum(ull v) {
    float lo, hi;
    asm("mov.b64 {%0, %1}, %2;" : "=f"(lo), "=f"(hi) : "l"(v));
    return lo + hi;
}

// ---- z = tanh(A[:, :Z]) + noise * exp(A[:, Z:]) ----
__global__ __launch_bounds__(256) void z_kernel(const float* __restrict__ A,
                                                const float* __restrict__ nz) {
    int i = blockIdx.x * 256 + threadIdx.x;
    if (i >= B_ * T_ * Z_) return;
    int m = i >> 5, z = i & 31;
    g_z[i] = tanh_s(A[(size_t)m * 64 + z]) + nz[i] * __expf(A[(size_t)m * 64 + 32 + z]);
}

// ---- U = hd@Whd2h^T + z@Wz2h^T + bias : M=128000 N=256 K=288, dbl-buffered ----
__global__ __launch_bounds__(256, 1) void u_gemm(const float* __restrict__ hd,
                                                 const float* __restrict__ Wh,
                                                 const float* __restrict__ Wz,
                                                 const float* __restrict__ bias) {
    __shared__ float As[2][8][128], Bs[2][8][128];
    int tid = threadIdx.x;
    int mB = blockIdx.y * 128, nB = blockIdx.x * 128;
    int lr = tid >> 1, lk = (tid & 1) << 2;
    int tr = (tid >> 4) << 3, tc = (tid & 15) << 3;
    float acc[8][8];
#pragma unroll
    for (int i = 0; i < 8; i++)
#pragma unroll
        for (int j = 0; j < 8; j++) acc[i][j] = 0.f;

    const float* aH = hd + (size_t)(mB + lr) * 256 + lk;
    const float* bH = Wh + (size_t)(nB + lr) * 256 + lk;
    const float* aZ = g_z + (size_t)(mB + lr) * 32 + lk;
    const float* bZ = Wz + (size_t)(nB + lr) * 32 + lk;

    float4 av = *(const float4*)(aH);
    float4 bv = *(const float4*)(bH);
    As[0][lk][lr] = av.x; As[0][lk + 1][lr] = av.y; As[0][lk + 2][lr] = av.z; As[0][lk + 3][lr] = av.w;
    Bs[0][lk][lr] = bv.x; Bs[0][lk + 1][lr] = bv.y; Bs[0][lk + 2][lr] = bv.z; Bs[0][lk + 3][lr] = bv.w;
    __syncthreads();

    int p = 0;
    for (int k0 = 0; k0 < 288; k0 += 8) {
        float4 nav, nbv;
        bool more = (k0 < 280);
        if (more) {
            int kn = k0 + 8;
            if (kn < 256) {
                nav = *(const float4*)(aH + kn);
                nbv = *(const float4*)(bH + kn);
            } else {
                nav = *(const float4*)(aZ + (kn - 256));
                nbv = *(const float4*)(bZ + (kn - 256));
            }
        }
#pragma unroll
        for (int kk = 0; kk < 8; kk++) {
            float mf[8], nf[8];
            *(float4*)mf = *(const float4*)&As[p][kk][tr];
            *(float4*)(mf + 4) = *(const float4*)&As[p][kk][tr + 4];
            *(float4*)nf = *(const float4*)&Bs[p][kk][tc];
            *(float4*)(nf + 4) = *(const float4*)&Bs[p][kk][tc + 4];
#pragma unroll
            for (int i = 0; i < 8; i++)
#pragma unroll
                for (int j = 0; j < 8; j++) acc[i][j] += mf[i] * nf[j];
        }
        if (more) {
            int q = p ^ 1;
            As[q][lk][lr] = nav.x; As[q][lk + 1][lr] = nav.y; As[q][lk + 2][lr] = nav.z; As[q][lk + 3][lr] = nav.w;
            Bs[q][lk][lr] = nbv.x; Bs[q][lk + 1][lr] = nbv.y; Bs[q][lk + 2][lr] = nbv.z; Bs[q][lk + 3][lr] = nbv.w;
            p = q;
            __syncthreads();
        }
    }
    float bj[8];
#pragma unroll
    for (int j = 0; j < 8; j++) bj[j] = bias[nB + tc + j];
#pragma unroll
    for (int i = 0; i < 8; i++) {
        float* o = g_U + (size_t)(mB + tr + i) * 256 + nB + tc;
#pragma unroll
        for (int j = 0; j < 8; j++) o[j] = acc[i][j] + bj[j];
    }
}

// ---- wnll_init_h ----
__global__ __launch_bounds__(256) void wnll_kernel(const float* __restrict__ ih,
                                                   const float* __restrict__ mu,
                                                   float* __restrict__ out) {
    __shared__ float sr[8];
    int tid = threadIdx.x;
    float s = 0.f;
    for (int i = tid; i < B_ * D_; i += 256) {
        float d = ih[i] - mu[i & 255];
        s += 0.5f * d * d + 0.91893853320467274f;
    }
#pragma unroll
    for (int o = 16; o > 0; o >>= 1) s += __shfl_down_sync(~0u, s, o);
    if ((tid & 31) == 0) sr[tid >> 5] = s;
    __syncthreads();
    if (tid == 0) {
        float t = 0.f;
        for (int i = 0; i < 8; i++) t += sr[i];
        out[NOUT + 1] = 0.001f * t / 256.0f;
    }
}

// ---- kl final reduce ----
__global__ void kl_final(float* __restrict__ out) {
    if (threadIdx.x == 0) {
        float s = 0.f;
        for (int i = 0; i < 64; i++) s += g_kl[i];
        out[NOUT] = 0.001f / 32.0f * s;
    }
}

// ---- sequential scan: weights in registers + f32x2 packed FMA ----
__global__ void __cluster_dims__(2, 1, 1) __launch_bounds__(STH, 1)
seq_kernel(const float* __restrict__ A, const float* __restrict__ in_p0,
           const float* __restrict__ Wd2h, const float* __restrict__ Wd2z,
           const float* __restrict__ initH, float* __restrict__ out) {
    __shared__ float dbuf[1088];   // [2 buf][2 b][272]
    __shared__ float dzs[256];     // [2 buf][2 b][64]
    __shared__ float sred[16];

    const int tid = threadIdx.x;
    const int rank = blockIdx.x & 1;
    const int c = blockIdx.x >> 1;
    const int warp = tid >> 5, lane = tid & 31;
    const int j4sub = lane & 3, ks = lane >> 2;
    const int ks4 = ks * 4;
    const int jcol = (warp * 4 + j4sub) * 4;
    const int jsel = ((ks & 2) ? 2 : 0) + ((ks & 4) ? 1 : 0);
    const int jmine = jcol + jsel;
    const int bmine = ks & 1;
    const int ng = rank * 160 + jmine;
    const bool has_h = (ng < 256);
    const int b_u = 2 * c + bmine;
    const float dec  = (ng < 128) ? 0.75f : 0.5f;
    const float itau = (ng < 128) ? 0.25f : 0.5f;

    const bool isKL = (rank == 1) && (tid < 64);
    const int klb = tid >> 5, klz = tid & 31;
    float p0m = 0.f, p0s = 0.f, amu_p = 0.f, als_p = 0.f;
    const float* Ap = A + (size_t)(2 * c + klb) * T_ * 64;
    if (isKL) {
        p0m = in_p0[(2 * c + klb) * 64 + klz];
        p0s = in_p0[(2 * c + klb) * 64 + 32 + klz];
    }

    // ---- load this thread's weights into registers as packed k-pairs ----
    // w2[i][p][j] = ( W[n][k], W[n][k+1] ), n = rank*160+jcol+j, k = ks4+32i+2p
    ull w2[8][2][4];
#pragma unroll
    for (int i = 0; i < 8; i++)
#pragma unroll
        for (int p = 0; p < 2; p++)
#pragma unroll
            for (int j = 0; j < 4; j++) {
                int n = rank * 160 + jcol + j;
                int k = ks4 + 32 * i + 2 * p;
                const float* src = (n < 256) ? (Wd2h + n * 256 + k)
                                             : (Wd2z + (n - 256) * 256 + k);
                float w0 = __ldg(src), w1 = __ldg(src + 1);
                asm("mov.b64 %0, {%1, %2};" : "=l"(w2[i][p][j]) : "f"(w0), "f"(w1));
            }

    // d0 = tanh(init_h), both batches
    for (int i = tid; i < 512; i += STH) {
        int bb = i >> 8, k = i & 255;
        dbuf[bb * 272 + k] = tanh_s(initH[(2 * c + bb) * 256 + k]);
    }
    float h = 0.f, u_pf = 0.f;
    const float* Up = g_U;
    float* Op = out;
    if (has_h) {
        h = initH[b_u * 256 + ng];
        Up = g_U + (size_t)b_u * T_ * 256 + ng;
        Op = out + (size_t)b_u * T_ * 256 + ng;
    }
    const uint32_t dl = smem_u32(dbuf);
    uint32_t dp;
    asm("mapa.shared::cluster.u32 %0, %1, %2;" : "=r"(dp) : "r"(dl), "r"(rank ^ 1));

    __syncthreads();
    asm volatile("barrier.cluster.arrive.aligned;\n\tbarrier.cluster.wait.aligned;" ::: "memory");

    if (has_h) u_pf = __ldg(Up);

    float klacc = 0.f;
    int cur = 0;
    for (int t = 0; t < T_; ++t) {
        if (t > 0) asm volatile("barrier.cluster.wait.aligned;" ::: "memory");

        // deferred KL for step t-1
        if (isKL && t > 0) {
            float mq = tanh_s(amu_p), sq = __expf(als_p);
            float pm, ps;
            if (t == 1) { pm = p0m; ps = p0s; }
            else {
                const float* dzp = dzs + ((t - 1) & 1) * 128 + klb * 64;
                pm = dzp[klz]; ps = dzp[32 + klz];
            }
            float mp = tanh_s(pm), sp = __expf(ps);
            float dm = mq - mp;
            klacc += __logf(sp + EPS_) - __logf(sq + EPS_) - 0.5f
                   + 0.5f * (dm * dm + sq * sq) / (sp * sp + EPS_);
        }

        // GEMM phase: register weights, packed f32x2 FMA
        const float* dc = dbuf + cur * 544;
        ull acc[4][2];
#pragma unroll
        for (int j = 0; j < 4; j++) { acc[j][0] = 0ull; acc[j][1] = 0ull; }
#pragma unroll
        for (int i = 0; i < 8; i++) {
            int kr = ks4 + 32 * i;
            ull d0a = *(const ull*)(dc + kr);
            ull d0b = *(const ull*)(dc + kr + 2);
            ull d1a = *(const ull*)(dc + 272 + kr);
            ull d1b = *(const ull*)(dc + 272 + kr + 2);
#pragma unroll
            for (int j = 0; j < 4; j++) {
                ffma2(acc[j][0], w2[i][0][j], d0a);
                ffma2(acc[j][0], w2[i][1][j], d0b);
                ffma2(acc[j][1], w2[i][0][j], d1a);
                ffma2(acc[j][1], w2[i][1][j], d1b);
            }
        }
        float4 a0 = make_float4(unpack_sum(acc[0][0]), unpack_sum(acc[1][0]),
                                unpack_sum(acc[2][0]), unpack_sum(acc[3][0]));
        float4 a1 = make_float4(unpack_sum(acc[0][1]), unpack_sum(acc[1][1]),
                                unpack_sum(acc[2][1]), unpack_sum(acc[3][1]));

        // butterfly reduce over ks (lane bits 2,3,4), halving payload
        float4 keep, send;
        if (bmine) { keep = a1; send = a0; } else { keep = a0; send = a1; }
        keep.x += __shfl_xor_sync(~0u, send.x, 4);
        keep.y += __shfl_xor_sync(~0u, send.y, 4);
        keep.z += __shfl_xor_sync(~0u, send.z, 4);
        keep.w += __shfl_xor_sync(~0u, send.w, 4);
        float k2x, k2y, s2x, s2y;
        if (ks & 2) { k2x = keep.z; k2y = keep.w; s2x = keep.x; s2y = keep.y; }
        else        { k2x = keep.x; k2y = keep.y; s2x = keep.z; s2y = keep.w; }
        k2x += __shfl_xor_sync(~0u, s2x, 8);
        k2y += __shfl_xor_sync(~0u, s2y, 8);
        float k3, s3;
        if (ks & 4) { k3 = k2y; s3 = k2x; } else { k3 = k2x; s3 = k2y; }
        float f = k3 + __shfl_xor_sync(~0u, s3, 16);

        int nxt = cur ^ 1;
        if (has_h) {
            h = dec * h + itau * (f + u_pf);
            float dn = tanh_s(h);
            int off = nxt * 544 + bmine * 272 + ng;
            dbuf[off] = dn;
            asm volatile("st.shared::cluster.b32 [%0], %1;" :: "r"(dp + (uint32_t)(off * 4)),
                         "r"(__float_as_uint(dn)) : "memory");
            *Op = dn;
            Op += 256;
        } else {
            dzs[(t & 1) * 128 + bmine * 64 + (jmine - 96)] = f;
        }

        asm volatile("barrier.cluster.arrive.aligned;" ::: "memory");

        if (has_h && t + 1 < T_) {
            Up += 256;
            u_pf = __ldg(Up);
        }
        if (isKL) {
            amu_p = __ldg(Ap + klz);
            als_p = __ldg(Ap + 32 + klz);
            Ap += 64;
        }
        cur = nxt;
    }
    asm volatile("barrier.cluster.wait.aligned;" ::: "memory");

    if (isKL) {
        float mq = tanh_s(amu_p), sq = __expf(als_p);
        const float* dzp = dzs + ((T_ - 1) & 1) * 128 + klb * 64;
        float mp = tanh_s(dzp[klz]), sp = __expf(dzp[32 + klz]);
        float dm = mq - mp;
        klacc += __logf(sp + EPS_) - __logf(sq + EPS_) - 0.5f
               + 0.5f * (dm * dm + sq * sq) / (sp * sp + EPS_);
    }
    if (rank == 1) {
        float v = (tid < 64) ? klacc : 0.f;
#pragma unroll
        for (int o = 16; o > 0; o >>= 1) v += __shfl_down_sync(~0u, v, o);
        if (lane == 0) sred[warp] = v;
        __syncthreads();
        if (tid == 0) {
            float s = 0.f;
            for (int w = 0; w < 10; w++) s += sred[w];
            g_kl[c] = s;
        }
    }
}

extern "C" void kernel_launch(void* const* d_in, const int* in_sizes, int n_in,
                              void* d_out, int out_size) {
    const float* hd    = (const float*)d_in[0];
    const float* A     = (const float*)d_in[1];
    const float* in_p0 = (const float*)d_in[2];
    const float* noise = (const float*)d_in[3];
    const float* Wd2h  = (const float*)d_in[4];
    const float* Wz2h  = (const float*)d_in[5];
    const float* Wd2z  = (const float*)d_in[6];
    const float* Whd2h = (const float*)d_in[7];
    const float* biasd = (const float*)d_in[8];
    const float* initH = (const float*)d_in[9];
    const float* ihmu  = (const float*)d_in[10];
    float* out = (float*)d_out;

    z_kernel<<<(B_ * T_ * Z_ + 255) / 256, 256>>>(A, noise);
    u_gemm<<<dim3(2, 1000), 256>>>(hd, Whd2h, Wz2h, biasd);
    wnll_kernel<<<1, 256>>>(initH, ihmu, out);

    seq_kernel<<<128, STH>>>(A, in_p0, Wd2h, Wd2z, initH, out);
    kl_final<<<1, 32>>>(out);
}